// round 5
// baseline (speedup 1.0000x reference)
#include <cuda_runtime.h>
#include <cuda_bf16.h>
#include <cstdint>

// ---------------------------------------------------------------------------
// NetVLAD on GB300 — round 4: mma.sync bf16x3 convs with pre-split packed
// bf16 activations (hi|lo<<16 in one uint32) + split-K assign/softmax.
// ---------------------------------------------------------------------------

#define N_IMG   16
#define CHN     512
#define HWP     1024
#define KCL     64
#define KTOT    4608     // 9 taps * 512 ic
#define AP      40       // SMEM row pitch in bf16 (80B -> conflict-free ldmatrix)

// -------- device scratch --------
__device__ __align__(16) __nv_bfloat16 g_w1h[CHN * KTOT];
__device__ __align__(16) __nv_bfloat16 g_w1l[CHN * KTOT];
__device__ __align__(16) __nv_bfloat16 g_w2h[CHN * KTOT];
__device__ __align__(16) __nv_bfloat16 g_w2l[CHN * KTOT];
__device__ __align__(16) uint32_t g_xp[N_IMG * CHN * HWP]; // packed input
__device__ __align__(16) uint32_t g_hp[N_IMG * CHN * HWP]; // packed conv1 out
__device__ float g_invn[N_IMG * HWP];
__device__ float g_sa[N_IMG * KCL * HWP];
__device__ float g_ssum[N_IMG * KCL];
__device__ float g_vlad[N_IMG * KCL * CHN];
__device__ float g_rowss[N_IMG * KCL];
__device__ float g_bns[CHN];
__device__ float g_bnb[CHN];

// -------- helpers --------
__device__ __forceinline__ uint32_t smem_u32(const void* p) {
    uint32_t a;
    asm("{ .reg .u64 t; cvta.to.shared.u64 t, %1; cvt.u32.u64 %0, t; }"
        : "=r"(a) : "l"(p));
    return a;
}
__device__ __forceinline__ void ldm_x4(uint32_t r[4], uint32_t addr) {
    asm volatile("ldmatrix.sync.aligned.m8n8.x4.shared.b16 {%0,%1,%2,%3}, [%4];"
                 : "=r"(r[0]), "=r"(r[1]), "=r"(r[2]), "=r"(r[3]) : "r"(addr));
}
__device__ __forceinline__ void mma_bf16(float c[4], const uint32_t a[4],
                                         uint32_t b0, uint32_t b1) {
    asm volatile(
        "mma.sync.aligned.m16n8k16.row.col.f32.bf16.bf16.f32 "
        "{%0,%1,%2,%3}, {%4,%5,%6,%7}, {%8,%9}, {%0,%1,%2,%3};"
        : "+f"(c[0]), "+f"(c[1]), "+f"(c[2]), "+f"(c[3])
        : "r"(a[0]), "r"(a[1]), "r"(a[2]), "r"(a[3]), "r"(b0), "r"(b1));
}
// value -> (hi bf16 in low half, lo bf16 in high half)
__device__ __forceinline__ uint32_t pack_hl(float v) {
    __nv_bfloat16 h = __float2bfloat16(v);
    __nv_bfloat16 l = __float2bfloat16(v - __bfloat162float(h));
    return (uint32_t)__bfloat16_as_ushort(h) |
           ((uint32_t)__bfloat16_as_ushort(l) << 16);
}

// ======================= prep: weight hi/lo split + BN fold ================
__global__ void prep_kernel(const float* __restrict__ w1,
                            const float* __restrict__ w2,
                            const float* __restrict__ gamma,
                            const float* __restrict__ beta,
                            const float* __restrict__ mean,
                            const float* __restrict__ var) {
    int idx = blockIdx.x * 256 + threadIdx.x;
    const int per = CHN * KTOT;
    if (idx < 2 * per) {
        int which = (idx >= per) ? 1 : 0;
        int r = idx - which * per;
        int oc = r / KTOT;
        int rr = r - oc * KTOT;
        int tap = rr >> 9;
        int ic = rr & 511;
        const float* w = which ? w2 : w1;
        float v = w[oc * 4608 + ic * 9 + tap];
        __nv_bfloat16 h = __float2bfloat16(v);
        __nv_bfloat16 l = __float2bfloat16(v - __bfloat162float(h));
        if (which) { g_w2h[r] = h; g_w2l[r] = l; }
        else       { g_w1h[r] = h; g_w1l[r] = l; }
    }
    if (idx < CHN) {
        float inv = rsqrtf(var[idx] + 1e-5f);
        float s = gamma[idx] * inv;
        g_bns[idx] = s;
        g_bnb[idx] = beta[idx] - mean[idx] * s;
    }
}

// ======================= pack x: fp32 -> packed bf16 hi/lo =================
__global__ void pack_x_kernel(const float* __restrict__ x) {
    int idx = blockIdx.x * 256 + threadIdx.x;   // grid covers N*C*HWP
    float4 v = reinterpret_cast<const float4*>(x)[idx];
    uint4 o;
    o.x = pack_hl(v.x); o.y = pack_hl(v.y);
    o.z = pack_hl(v.z); o.w = pack_hl(v.w);
    reinterpret_cast<uint4*>(g_xp)[idx] = o;
}

// ======================= conv3x3 implicit GEMM (mma.sync bf16x3) ===========
// CTA: 128 oc x 128 positions. 8 warps, warp tile 64x32.
// K chunks of 32 (tap-aligned). Grid: (8 ptiles, 4 octiles, 16 n).
// which==1: in g_xp -> out g_hp (packed, BN+ReLU). which==2: g_hp -> fp32.
__global__ void __launch_bounds__(256, 2)
conv_mma_kernel(float* __restrict__ out_ext, int which) {
    __shared__ __align__(16) __nv_bfloat16 sAh[128 * AP];
    __shared__ __align__(16) __nv_bfloat16 sAl[128 * AP];
    __shared__ __align__(16) __nv_bfloat16 sBh[128 * AP];
    __shared__ __align__(16) __nv_bfloat16 sBl[128 * AP];

    const int tid = threadIdx.x;
    const int lane = tid & 31, warp = tid >> 5;
    const int wm = warp >> 2, wn = warp & 3;
    const int n = blockIdx.z;
    const int oc0 = blockIdx.y * 128;
    const int p0 = blockIdx.x * 128;
    const int ybase = blockIdx.x * 4;

    const uint32_t* inP = ((which == 1) ? g_xp : g_hp) + (size_t)n * CHN * HWP;
    const __nv_bfloat16* wh = (which == 1) ? g_w1h : g_w2h;
    const __nv_bfloat16* wl = (which == 1) ? g_w1l : g_w2l;

    const uint32_t aAh = smem_u32(sAh), aAl = smem_u32(sAl);
    const uint32_t aBh = smem_u32(sBh), aBl = smem_u32(sBl);

    const int fa_oc = tid >> 1, fa_half = tid & 1;   // A: 16 bf16 per thread
    const int fb_p = tid & 127, fb_half = tid >> 7;  // B: 16 ic per thread

    const int lt = lane >> 3, lr = lane & 7;
    const int a_row_off = (lt & 1) * 8 + lr;
    const int a_col_off = (lt >> 1) * 8;
    const int b_row_off = (lt >> 1) * 8 + lr;
    const int b_col_off = (lt & 1) * 8;

    float C[4][4][4];
#pragma unroll
    for (int mi = 0; mi < 4; mi++)
#pragma unroll
        for (int ni = 0; ni < 4; ni++)
#pragma unroll
            for (int q = 0; q < 4; q++) C[mi][ni][q] = 0.f;

    for (int chunk = 0; chunk < 144; ++chunk) {
        const int k0 = chunk << 5;
        const int tap = k0 >> 9;
        const int icb = k0 & 511;
        const int dy = tap / 3 - 1, dx = tap % 3 - 1;

        // ---- A fill: 128 oc x 32 k, hi + lo (vectorized copies) ----
        {
            const uint4* sh = reinterpret_cast<const uint4*>(
                wh + (size_t)(oc0 + fa_oc) * KTOT + k0 + fa_half * 16);
            const uint4* sl = reinterpret_cast<const uint4*>(
                wl + (size_t)(oc0 + fa_oc) * KTOT + k0 + fa_half * 16);
            uint4 h0 = sh[0], h1 = sh[1];
            uint4 l0 = sl[0], l1 = sl[1];
            uint4* dh = reinterpret_cast<uint4*>(sAh + fa_oc * AP + fa_half * 16);
            uint4* dl = reinterpret_cast<uint4*>(sAl + fa_oc * AP + fa_half * 16);
            dh[0] = h0; dh[1] = h1;
            dl[0] = l0; dl[1] = l1;
        }

        // ---- B fill: 128 positions x 32 ic from packed input ----
        {
            int y = ybase + (fb_p >> 5) + dy;
            int x = (fb_p & 31) + dx;
            bool ok = ((unsigned)y < 32u) && ((unsigned)x < 32u);
            const uint32_t* src = inP + (size_t)(icb + fb_half * 16) * HWP +
                                  (y << 5) + x;
            uint32_t hp[8], lp[8];
#pragma unroll
            for (int q = 0; q < 8; q++) {
                uint32_t e0 = ok ? src[(2 * q) * HWP] : 0u;
                uint32_t e1 = ok ? src[(2 * q + 1) * HWP] : 0u;
                hp[q] = __byte_perm(e0, e1, 0x5410);
                lp[q] = __byte_perm(e0, e1, 0x7632);
            }
            uint4* dh = reinterpret_cast<uint4*>(sBh + fb_p * AP + fb_half * 16);
            uint4* dl = reinterpret_cast<uint4*>(sBl + fb_p * AP + fb_half * 16);
            dh[0] = make_uint4(hp[0], hp[1], hp[2], hp[3]);
            dh[1] = make_uint4(hp[4], hp[5], hp[6], hp[7]);
            dl[0] = make_uint4(lp[0], lp[1], lp[2], lp[3]);
            dl[1] = make_uint4(lp[4], lp[5], lp[6], lp[7]);
        }
        __syncthreads();

#pragma unroll
        for (int s = 0; s < 2; ++s) {
            const int kk0 = s * 16;
            uint32_t Af[4][4], Bhf[2][4], Blf[2][4];
#pragma unroll
            for (int mi = 0; mi < 4; mi++) {
                int row = wm * 64 + mi * 16 + a_row_off;
                ldm_x4(Af[mi], aAh + (uint32_t)(row * AP + kk0 + a_col_off) * 2);
            }
#pragma unroll
            for (int g = 0; g < 2; g++) {
                int row = wn * 32 + g * 16 + b_row_off;
                uint32_t off = (uint32_t)(row * AP + kk0 + b_col_off) * 2;
                ldm_x4(Bhf[g], aBh + off);
                ldm_x4(Blf[g], aBl + off);
            }
#pragma unroll
            for (int mi = 0; mi < 4; mi++)
#pragma unroll
                for (int ni = 0; ni < 4; ni++)
                    mma_bf16(C[mi][ni], Af[mi],
                             Bhf[ni >> 1][(ni & 1) * 2],
                             Bhf[ni >> 1][(ni & 1) * 2 + 1]);
#pragma unroll
            for (int mi = 0; mi < 4; mi++)
#pragma unroll
                for (int ni = 0; ni < 4; ni++)
                    mma_bf16(C[mi][ni], Af[mi],
                             Blf[ni >> 1][(ni & 1) * 2],
                             Blf[ni >> 1][(ni & 1) * 2 + 1]);
#pragma unroll
            for (int mi = 0; mi < 4; mi++) {
                int row = wm * 64 + mi * 16 + a_row_off;
                ldm_x4(Af[mi], aAl + (uint32_t)(row * AP + kk0 + a_col_off) * 2);
            }
#pragma unroll
            for (int mi = 0; mi < 4; mi++)
#pragma unroll
                for (int ni = 0; ni < 4; ni++)
                    mma_bf16(C[mi][ni], Af[mi],
                             Bhf[ni >> 1][(ni & 1) * 2],
                             Bhf[ni >> 1][(ni & 1) * 2 + 1]);
        }
        __syncthreads();
    }

    // ---- epilogue ----
    const int g = lane >> 2, t4 = lane & 3;
    if (which == 1) {
        uint32_t* outN = g_hp + (size_t)n * CHN * HWP;
#pragma unroll
        for (int mi = 0; mi < 4; mi++) {
            int ocA = oc0 + wm * 64 + mi * 16 + g;
            int ocB = ocA + 8;
            float sA = g_bns[ocA], bA = g_bnb[ocA];
            float sB = g_bns[ocB], bB = g_bnb[ocB];
#pragma unroll
            for (int ni = 0; ni < 4; ni++) {
                int nn = p0 + wn * 32 + ni * 8 + t4 * 2;
                float v0 = fmaxf(fmaf(C[mi][ni][0], sA, bA), 0.f);
                float v1 = fmaxf(fmaf(C[mi][ni][1], sA, bA), 0.f);
                float v2 = fmaxf(fmaf(C[mi][ni][2], sB, bB), 0.f);
                float v3 = fmaxf(fmaf(C[mi][ni][3], sB, bB), 0.f);
                *reinterpret_cast<uint2*>(&outN[(size_t)ocA * HWP + nn]) =
                    make_uint2(pack_hl(v0), pack_hl(v1));
                *reinterpret_cast<uint2*>(&outN[(size_t)ocB * HWP + nn]) =
                    make_uint2(pack_hl(v2), pack_hl(v3));
            }
        }
    } else {
        float* outN = out_ext + (size_t)n * CHN * HWP;
#pragma unroll
        for (int mi = 0; mi < 4; mi++) {
            int ocA = oc0 + wm * 64 + mi * 16 + g;
            int ocB = ocA + 8;
#pragma unroll
            for (int ni = 0; ni < 4; ni++) {
                int nn = p0 + wn * 32 + ni * 8 + t4 * 2;
                *reinterpret_cast<float2*>(&outN[(size_t)ocA * HWP + nn]) =
                    make_float2(C[mi][ni][0], C[mi][ni][1]);
                *reinterpret_cast<float2*>(&outN[(size_t)ocB * HWP + nn]) =
                    make_float2(C[mi][ni][2], C[mi][ni][3]);
            }
        }
    }
}

// ======================= assign + softmax (split-K x2) =======================
__global__ void __launch_bounds__(256)
assign_softmax_kernel(const float* __restrict__ xenc, const float* __restrict__ wa) {
    __shared__ float s_w[2][8][64];
    __shared__ float s_part[128][65];
    const int n = blockIdx.x >> 3;
    const int l0 = (blockIdx.x & 7) * 128;
    const int tid = threadIdx.x;
    const int grp = tid >> 7;           // 0: c 0..255, 1: c 256..511
    const int lt = tid & 127;
    const int l = l0 + lt;
    const int cbase = grp * 256;
    const float* xN = xenc + (size_t)n * CHN * HWP;

    float s[64];
#pragma unroll
    for (int k = 0; k < 64; k++) s[k] = 0.f;
    float ss = 0.f;

    for (int c0 = 0; c0 < 256; c0 += 8) {
#pragma unroll
        for (int r = 0; r < 4; r++) {
            int idx = lt + r * 128;
            int cc = idx >> 6, k = idx & 63;
            s_w[grp][cc][k] = wa[k * 512 + cbase + c0 + cc];
        }
        __syncthreads();
#pragma unroll
        for (int cc = 0; cc < 8; cc++) {
            float xv = xN[(cbase + c0 + cc) * HWP + l];
            ss = fmaf(xv, xv, ss);
#pragma unroll
            for (int k = 0; k < 64; k++) s[k] = fmaf(xv, s_w[grp][cc][k], s[k]);
        }
        __syncthreads();
    }

    if (grp == 1) {
#pragma unroll
        for (int k = 0; k < 64; k++) s_part[lt][k] = s[k];
        s_part[lt][64] = ss;
    }
    __syncthreads();
    if (grp == 0) {
#pragma unroll
        for (int k = 0; k < 64; k++) s[k] += s_part[lt][k];
        ss += s_part[lt][64];

        float invn = 1.f / fmaxf(sqrtf(ss), 1e-12f);
        g_invn[n * HWP + l] = invn;

        float mx = -1e30f;
#pragma unroll
        for (int k = 0; k < 64; k++) { s[k] *= invn; mx = fmaxf(mx, s[k]); }
        float sum = 0.f;
#pragma unroll
        for (int k = 0; k < 64; k++) { s[k] = expf(s[k] - mx); sum += s[k]; }
        float rs = 1.f / sum;
#pragma unroll
        for (int k = 0; k < 64; k++)
            g_sa[((size_t)n * 64 + k) * HWP + l] = s[k] * rs;
    }
}

// ======================= ssum =======================
__global__ void ssum_kernel() {
    int row = blockIdx.x;
    int tid = threadIdx.x;
    const float4* p = reinterpret_cast<const float4*>(g_sa + (size_t)row * HWP);
    float4 v = p[tid];
    float t = v.x + v.y + v.z + v.w;
    __shared__ float red[256];
    red[tid] = t;
    __syncthreads();
    for (int s = 128; s > 0; s >>= 1) {
        if (tid < s) red[tid] += red[tid + s];
        __syncthreads();
    }
    if (tid == 0) g_ssum[row] = red[0];
}

// ======================= VLAD =======================
__global__ void __launch_bounds__(256)
vlad_kernel(const float* __restrict__ xenc, const float* __restrict__ cent) {
    __shared__ float s_sa[8][1024];
    __shared__ float s_in[1024];
    const int n = blockIdx.x >> 3;
    const int k0 = (blockIdx.x & 7) * 8;
    const int tid = threadIdx.x;

    for (int i = tid; i < 1024; i += 256) s_in[i] = g_invn[n * HWP + i];
    for (int i = tid; i < 8192; i += 256) {
        int kk = i >> 10, l = i & 1023;
        s_sa[kk][l] = g_sa[((size_t)n * 64 + k0 + kk) * HWP + l];
    }
    __syncthreads();

    const int warp = tid >> 5, lane = tid & 31;
    const float* xN = xenc + (size_t)n * CHN * HWP;

    for (int c = warp; c < 512; c += 8) {
        float acc[8];
#pragma unroll
        for (int kk = 0; kk < 8; kk++) acc[kk] = 0.f;
        for (int l = lane; l < 1024; l += 32) {
            float xv = xN[c * HWP + l] * s_in[l];
#pragma unroll
            for (int kk = 0; kk < 8; kk++) acc[kk] = fmaf(xv, s_sa[kk][l], acc[kk]);
        }
#pragma unroll
        for (int kk = 0; kk < 8; kk++) {
            float v = acc[kk];
#pragma unroll
            for (int o = 16; o > 0; o >>= 1) v += __shfl_down_sync(0xffffffffu, v, o);
            if (lane == 0) {
                int k = k0 + kk;
                g_vlad[((size_t)n * 64 + k) * 512 + c] =
                    v - g_ssum[n * 64 + k] * cent[k * 512 + c];
            }
        }
    }
}

// ======================= intra norm =======================
__global__ void intra_kernel(float* __restrict__ out_vlad) {
    int row = blockIdx.x;
    int tid = threadIdx.x;
    const float2* p = reinterpret_cast<const float2*>(g_vlad + (size_t)row * 512);
    float2 v = p[tid];
    float ssq = v.x * v.x + v.y * v.y;
    __shared__ float red[256];
    red[tid] = ssq;
    __syncthreads();
    for (int s = 128; s > 0; s >>= 1) {
        if (tid < s) red[tid] += red[tid + s];
        __syncthreads();
    }
    float ss = red[0];
    float inv = 1.f / fmaxf(sqrtf(ss), 1e-12f);
    float2* o = reinterpret_cast<float2*>(out_vlad + (size_t)row * 512);
    float2 w;
    w.x = v.x * inv;
    w.y = v.y * inv;
    o[tid] = w;
    if (tid == 0) g_rowss[row] = ss * inv * inv;
}

// ======================= global scale =======================
__global__ void gscale_kernel(float* __restrict__ out_vlad) {
    int n = blockIdx.x;
    int tid = threadIdx.x;
    __shared__ float red[64];
    __shared__ float gsc;
    if (tid < 64) red[tid] = g_rowss[n * 64 + tid];
    __syncthreads();
    if (tid == 0) {
        float t = 0.f;
        for (int i = 0; i < 64; i++) t += red[i];
        gsc = 1.f / fmaxf(sqrtf(t), 1e-12f);
    }
    __syncthreads();
    float g = gsc;
    float* o = out_vlad + (size_t)n * (KCL * CHN);
    for (int i = tid; i < KCL * CHN; i += 256) o[i] *= g;
}

// ======================= launcher =======================
extern "C" void kernel_launch(void* const* d_in, const int* in_sizes, int n_in,
                              void* d_out, int out_size) {
    const float* x     = (const float*)d_in[0];
    const float* w1    = (const float*)d_in[1];
    const float* gamma = (const float*)d_in[2];
    const float* beta  = (const float*)d_in[3];
    const float* mean  = (const float*)d_in[4];
    const float* var   = (const float*)d_in[5];
    const float* w2    = (const float*)d_in[6];
    const float* wa    = (const float*)d_in[7];
    const float* cent  = (const float*)d_in[8];

    float* out = (float*)d_out;
    float* out_vlad = out;
    float* out_xenc = out + (size_t)N_IMG * KCL * CHN;

    prep_kernel<<<18432, 256>>>(w1, w2, gamma, beta, mean, var);
    pack_x_kernel<<<(N_IMG * CHN * HWP / 4) / 256, 256>>>(x);

    dim3 cgrid(8, 4, N_IMG);
    conv_mma_kernel<<<cgrid, 256>>>(nullptr, 1);
    conv_mma_kernel<<<cgrid, 256>>>(out_xenc, 2);

    assign_softmax_kernel<<<N_IMG * 8, 256>>>(out_xenc, wa);
    ssum_kernel<<<N_IMG * KCL, 256>>>();
    vlad_kernel<<<N_IMG * 8, 256>>>(out_xenc, cent);
    intra_kernel<<<N_IMG * KCL, 256>>>(out_vlad);
    gscale_kernel<<<N_IMG, 256>>>(out_vlad);
}

// round 6
// speedup vs baseline: 1.0410x; 1.0410x over previous
#include <cuda_runtime.h>
#include <cuda_bf16.h>
#include <cstdint>

// ---------------------------------------------------------------------------
// NetVLAD on GB300 — round 5: software-pipelined bf16x3 mma.sync convs
// (double-buffered SMEM, cp.async A tiles, register-staged B tiles).
// ---------------------------------------------------------------------------

#define N_IMG   16
#define CHN     512
#define HWP     1024
#define KCL     64
#define KTOT    4608
#define AP      40          // SMEM row pitch in bf16 (80B)

// stage layout (bytes): sAh 0, sAl 10240, sBh 20480, sBl 30720
#define STAGE_BYTES 40960
#define OFF_AL 10240
#define OFF_BH 20480
#define OFF_BL 30720
#define CONV_DSMEM (2 * STAGE_BYTES)

// -------- device scratch --------
__device__ __align__(16) __nv_bfloat16 g_w1h[CHN * KTOT];
__device__ __align__(16) __nv_bfloat16 g_w1l[CHN * KTOT];
__device__ __align__(16) __nv_bfloat16 g_w2h[CHN * KTOT];
__device__ __align__(16) __nv_bfloat16 g_w2l[CHN * KTOT];
__device__ __align__(16) uint32_t g_xp[N_IMG * CHN * HWP]; // packed input
__device__ __align__(16) uint32_t g_hp[N_IMG * CHN * HWP]; // packed conv1 out
__device__ float g_invn[N_IMG * HWP];
__device__ float g_sa[N_IMG * KCL * HWP];
__device__ float g_ssum[N_IMG * KCL];
__device__ float g_vlad[N_IMG * KCL * CHN];
__device__ float g_rowss[N_IMG * KCL];
__device__ float g_bns[CHN];
__device__ float g_bnb[CHN];

// -------- helpers --------
__device__ __forceinline__ uint32_t smem_u32(const void* p) {
    uint32_t a;
    asm("{ .reg .u64 t; cvta.to.shared.u64 t, %1; cvt.u32.u64 %0, t; }"
        : "=r"(a) : "l"(p));
    return a;
}
__device__ __forceinline__ void ldm_x4(uint32_t r[4], uint32_t addr) {
    asm volatile("ldmatrix.sync.aligned.m8n8.x4.shared.b16 {%0,%1,%2,%3}, [%4];"
                 : "=r"(r[0]), "=r"(r[1]), "=r"(r[2]), "=r"(r[3]) : "r"(addr));
}
__device__ __forceinline__ void mma_bf16(float c[4], const uint32_t a[4],
                                         uint32_t b0, uint32_t b1) {
    asm volatile(
        "mma.sync.aligned.m16n8k16.row.col.f32.bf16.bf16.f32 "
        "{%0,%1,%2,%3}, {%4,%5,%6,%7}, {%8,%9}, {%0,%1,%2,%3};"
        : "+f"(c[0]), "+f"(c[1]), "+f"(c[2]), "+f"(c[3])
        : "r"(a[0]), "r"(a[1]), "r"(a[2]), "r"(a[3]), "r"(b0), "r"(b1));
}
__device__ __forceinline__ void cp_async16(uint32_t dst, const void* src) {
    asm volatile("cp.async.cg.shared.global [%0], [%1], 16;"
                 :: "r"(dst), "l"(src));
}
#define CP_COMMIT() asm volatile("cp.async.commit_group;" ::: "memory")
#define CP_WAIT0()  asm volatile("cp.async.wait_group 0;" ::: "memory")

__device__ __forceinline__ uint32_t pack_hl(float v) {
    __nv_bfloat16 h = __float2bfloat16(v);
    __nv_bfloat16 l = __float2bfloat16(v - __bfloat162float(h));
    return (uint32_t)__bfloat16_as_ushort(h) |
           ((uint32_t)__bfloat16_as_ushort(l) << 16);
}

// ======================= prep =======================
__global__ void prep_kernel(const float* __restrict__ w1,
                            const float* __restrict__ w2,
                            const float* __restrict__ gamma,
                            const float* __restrict__ beta,
                            const float* __restrict__ mean,
                            const float* __restrict__ var) {
    int idx = blockIdx.x * 256 + threadIdx.x;
    const int per = CHN * KTOT;
    if (idx < 2 * per) {
        int which = (idx >= per) ? 1 : 0;
        int r = idx - which * per;
        int oc = r / KTOT;
        int rr = r - oc * KTOT;
        int tap = rr >> 9;
        int ic = rr & 511;
        const float* w = which ? w2 : w1;
        float v = w[oc * 4608 + ic * 9 + tap];
        __nv_bfloat16 h = __float2bfloat16(v);
        __nv_bfloat16 l = __float2bfloat16(v - __bfloat162float(h));
        if (which) { g_w2h[r] = h; g_w2l[r] = l; }
        else       { g_w1h[r] = h; g_w1l[r] = l; }
    }
    if (idx < CHN) {
        float inv = rsqrtf(var[idx] + 1e-5f);
        float s = gamma[idx] * inv;
        g_bns[idx] = s;
        g_bnb[idx] = beta[idx] - mean[idx] * s;
    }
}

// ======================= pack x =======================
__global__ void pack_x_kernel(const float* __restrict__ x) {
    int idx = blockIdx.x * 256 + threadIdx.x;
    float4 v = reinterpret_cast<const float4*>(x)[idx];
    uint4 o;
    o.x = pack_hl(v.x); o.y = pack_hl(v.y);
    o.z = pack_hl(v.z); o.w = pack_hl(v.w);
    reinterpret_cast<uint4*>(g_xp)[idx] = o;
}

// ======================= conv3x3: pipelined mma.sync bf16x3 ================
__global__ void __launch_bounds__(256, 2)
conv_mma_kernel(float* __restrict__ out_ext, int which) {
    extern __shared__ __align__(16) char dynsm[];
    const uint32_t smbase = smem_u32(dynsm);

    const int tid = threadIdx.x;
    const int lane = tid & 31, warp = tid >> 5;
    const int wm = warp >> 2, wn = warp & 3;
    const int n = blockIdx.z;
    const int oc0 = blockIdx.y * 128;
    const int p0 = blockIdx.x * 128;
    const int ybase = blockIdx.x * 4;

    const uint32_t* inP = ((which == 1) ? g_xp : g_hp) + (size_t)n * CHN * HWP;
    const __nv_bfloat16* wh = (which == 1) ? g_w1h : g_w2h;
    const __nv_bfloat16* wl = (which == 1) ? g_w1l : g_w2l;

    const int fa_oc = tid >> 1, fa_half = tid & 1;   // A: 32B hi + 32B lo
    const int fb_p = tid & 127, fb_half = tid >> 7;  // B: 16 ic per thread

    const int lt = lane >> 3, lr = lane & 7;
    const int a_row_off = (lt & 1) * 8 + lr;
    const int a_col_off = (lt >> 1) * 8;
    const int b_row_off = (lt >> 1) * 8 + lr;
    const int b_col_off = (lt & 1) * 8;

    float C[4][4][4];
#pragma unroll
    for (int mi = 0; mi < 4; mi++)
#pragma unroll
        for (int ni = 0; ni < 4; ni++)
#pragma unroll
            for (int q = 0; q < 4; q++) C[mi][ni][q] = 0.f;

    // ---- A prefetch via cp.async (4 x 16B per thread) ----
    auto fillA = [&](int chunk, int stage) {
        int k0 = chunk << 5;
        uint32_t dst = smbase + stage * STAGE_BYTES + fa_oc * (AP * 2) +
                       fa_half * 32;
        const __nv_bfloat16* srcH =
            wh + (size_t)(oc0 + fa_oc) * KTOT + k0 + fa_half * 16;
        const __nv_bfloat16* srcL =
            wl + (size_t)(oc0 + fa_oc) * KTOT + k0 + fa_half * 16;
        cp_async16(dst, srcH);
        cp_async16(dst + 16, srcH + 8);
        cp_async16(dst + OFF_AL, srcL);
        cp_async16(dst + OFF_AL + 16, srcL + 8);
    };

    // ---- B prefetch to regs ----
    auto loadB = [&](int chunk, uint32_t e[16]) {
        int k0 = chunk << 5;
        int tap = k0 >> 9;
        int icb = k0 & 511;
        int dy = tap / 3 - 1, dx = tap % 3 - 1;
        int y = ybase + (fb_p >> 5) + dy;
        int x = (fb_p & 31) + dx;
        bool ok = ((unsigned)y < 32u) && ((unsigned)x < 32u);
        const uint32_t* src = inP + (size_t)(icb + fb_half * 16) * HWP +
                              (y << 5) + x;
#pragma unroll
        for (int q = 0; q < 16; q++) e[q] = ok ? src[q * HWP] : 0u;
    };

    auto stsB = [&](const uint32_t e[16], int stage) {
        uint32_t hp[8], lp[8];
#pragma unroll
        for (int q = 0; q < 8; q++) {
            hp[q] = __byte_perm(e[2 * q], e[2 * q + 1], 0x5410);
            lp[q] = __byte_perm(e[2 * q], e[2 * q + 1], 0x7632);
        }
        uint32_t dst = smbase + stage * STAGE_BYTES + fb_p * (AP * 2) +
                       fb_half * 32;
        *reinterpret_cast<uint4*>(dynsm + (dst - smbase) + OFF_BH) =
            make_uint4(hp[0], hp[1], hp[2], hp[3]);
        *reinterpret_cast<uint4*>(dynsm + (dst - smbase) + OFF_BH + 16) =
            make_uint4(hp[4], hp[5], hp[6], hp[7]);
        *reinterpret_cast<uint4*>(dynsm + (dst - smbase) + OFF_BL) =
            make_uint4(lp[0], lp[1], lp[2], lp[3]);
        *reinterpret_cast<uint4*>(dynsm + (dst - smbase) + OFF_BL + 16) =
            make_uint4(lp[4], lp[5], lp[6], lp[7]);
    };

    // ---- prologue: stage 0 = chunk 0 ----
    {
        uint32_t e[16];
        fillA(0, 0);
        CP_COMMIT();
        loadB(0, e);
        stsB(e, 0);
        CP_WAIT0();
        __syncthreads();
    }

    for (int chunk = 0; chunk < 144; ++chunk) {
        const int stage = chunk & 1;
        const int nstage = stage ^ 1;
        const bool have = (chunk + 1) < 144;

        uint32_t e[16];
        if (have) {
            fillA(chunk + 1, nstage);
            CP_COMMIT();
            loadB(chunk + 1, e);
        }

        // ---- compute chunk from buf[stage] ----
        const uint32_t sb = smbase + stage * STAGE_BYTES;
#pragma unroll
        for (int s = 0; s < 2; ++s) {
            const int kk0 = s * 16;
            uint32_t Af[4][4], Bhf[2][4], Blf[2][4];
#pragma unroll
            for (int mi = 0; mi < 4; mi++) {
                int row = wm * 64 + mi * 16 + a_row_off;
                ldm_x4(Af[mi], sb + (uint32_t)(row * AP + kk0 + a_col_off) * 2);
            }
#pragma unroll
            for (int g = 0; g < 2; g++) {
                int row = wn * 32 + g * 16 + b_row_off;
                uint32_t off = (uint32_t)(row * AP + kk0 + b_col_off) * 2;
                ldm_x4(Bhf[g], sb + OFF_BH + off);
                ldm_x4(Blf[g], sb + OFF_BL + off);
            }
#pragma unroll
            for (int mi = 0; mi < 4; mi++)
#pragma unroll
                for (int ni = 0; ni < 4; ni++)
                    mma_bf16(C[mi][ni], Af[mi],
                             Bhf[ni >> 1][(ni & 1) * 2],
                             Bhf[ni >> 1][(ni & 1) * 2 + 1]);
#pragma unroll
            for (int mi = 0; mi < 4; mi++)
#pragma unroll
                for (int ni = 0; ni < 4; ni++)
                    mma_bf16(C[mi][ni], Af[mi],
                             Blf[ni >> 1][(ni & 1) * 2],
                             Blf[ni >> 1][(ni & 1) * 2 + 1]);
#pragma unroll
            for (int mi = 0; mi < 4; mi++) {
                int row = wm * 64 + mi * 16 + a_row_off;
                ldm_x4(Af[mi],
                       sb + OFF_AL + (uint32_t)(row * AP + kk0 + a_col_off) * 2);
            }
#pragma unroll
            for (int mi = 0; mi < 4; mi++)
#pragma unroll
                for (int ni = 0; ni < 4; ni++)
                    mma_bf16(C[mi][ni], Af[mi],
                             Bhf[ni >> 1][(ni & 1) * 2],
                             Bhf[ni >> 1][(ni & 1) * 2 + 1]);
        }

        if (have) stsB(e, nstage);
        CP_WAIT0();
        __syncthreads();
    }

    // ---- epilogue ----
    const int g = lane >> 2, t4 = lane & 3;
    if (which == 1) {
        uint32_t* outN = g_hp + (size_t)n * CHN * HWP;
#pragma unroll
        for (int mi = 0; mi < 4; mi++) {
            int ocA = oc0 + wm * 64 + mi * 16 + g;
            int ocB = ocA + 8;
            float sA = g_bns[ocA], bA = g_bnb[ocA];
            float sB = g_bns[ocB], bB = g_bnb[ocB];
#pragma unroll
            for (int ni = 0; ni < 4; ni++) {
                int nn = p0 + wn * 32 + ni * 8 + t4 * 2;
                float v0 = fmaxf(fmaf(C[mi][ni][0], sA, bA), 0.f);
                float v1 = fmaxf(fmaf(C[mi][ni][1], sA, bA), 0.f);
                float v2 = fmaxf(fmaf(C[mi][ni][2], sB, bB), 0.f);
                float v3 = fmaxf(fmaf(C[mi][ni][3], sB, bB), 0.f);
                *reinterpret_cast<uint2*>(&outN[(size_t)ocA * HWP + nn]) =
                    make_uint2(pack_hl(v0), pack_hl(v1));
                *reinterpret_cast<uint2*>(&outN[(size_t)ocB * HWP + nn]) =
                    make_uint2(pack_hl(v2), pack_hl(v3));
            }
        }
    } else {
        float* outN = out_ext + (size_t)n * CHN * HWP;
#pragma unroll
        for (int mi = 0; mi < 4; mi++) {
            int ocA = oc0 + wm * 64 + mi * 16 + g;
            int ocB = ocA + 8;
#pragma unroll
            for (int ni = 0; ni < 4; ni++) {
                int nn = p0 + wn * 32 + ni * 8 + t4 * 2;
                *reinterpret_cast<float2*>(&outN[(size_t)ocA * HWP + nn]) =
                    make_float2(C[mi][ni][0], C[mi][ni][1]);
                *reinterpret_cast<float2*>(&outN[(size_t)ocB * HWP + nn]) =
                    make_float2(C[mi][ni][2], C[mi][ni][3]);
            }
        }
    }
}

// ======================= assign + softmax (split-K x2) =====================
__global__ void __launch_bounds__(256)
assign_softmax_kernel(const float* __restrict__ xenc, const float* __restrict__ wa) {
    __shared__ float s_w[2][8][64];
    __shared__ float s_part[128][65];
    const int n = blockIdx.x >> 3;
    const int l0 = (blockIdx.x & 7) * 128;
    const int tid = threadIdx.x;
    const int grp = tid >> 7;
    const int lt = tid & 127;
    const int l = l0 + lt;
    const int cbase = grp * 256;
    const float* xN = xenc + (size_t)n * CHN * HWP;

    float s[64];
#pragma unroll
    for (int k = 0; k < 64; k++) s[k] = 0.f;
    float ss = 0.f;

    for (int c0 = 0; c0 < 256; c0 += 8) {
#pragma unroll
        for (int r = 0; r < 4; r++) {
            int idx = lt + r * 128;
            int cc = idx >> 6, k = idx & 63;
            s_w[grp][cc][k] = wa[k * 512 + cbase + c0 + cc];
        }
        __syncthreads();
#pragma unroll
        for (int cc = 0; cc < 8; cc++) {
            float xv = xN[(cbase + c0 + cc) * HWP + l];
            ss = fmaf(xv, xv, ss);
#pragma unroll
            for (int k = 0; k < 64; k++) s[k] = fmaf(xv, s_w[grp][cc][k], s[k]);
        }
        __syncthreads();
    }

    if (grp == 1) {
#pragma unroll
        for (int k = 0; k < 64; k++) s_part[lt][k] = s[k];
        s_part[lt][64] = ss;
    }
    __syncthreads();
    if (grp == 0) {
#pragma unroll
        for (int k = 0; k < 64; k++) s[k] += s_part[lt][k];
        ss += s_part[lt][64];

        float invn = 1.f / fmaxf(sqrtf(ss), 1e-12f);
        g_invn[n * HWP + l] = invn;

        float mx = -1e30f;
#pragma unroll
        for (int k = 0; k < 64; k++) { s[k] *= invn; mx = fmaxf(mx, s[k]); }
        float sum = 0.f;
#pragma unroll
        for (int k = 0; k < 64; k++) { s[k] = expf(s[k] - mx); sum += s[k]; }
        float rs = 1.f / sum;
#pragma unroll
        for (int k = 0; k < 64; k++)
            g_sa[((size_t)n * 64 + k) * HWP + l] = s[k] * rs;
    }
}

// ======================= ssum =======================
__global__ void ssum_kernel() {
    int row = blockIdx.x;
    int tid = threadIdx.x;
    const float4* p = reinterpret_cast<const float4*>(g_sa + (size_t)row * HWP);
    float4 v = p[tid];
    float t = v.x + v.y + v.z + v.w;
    __shared__ float red[256];
    red[tid] = t;
    __syncthreads();
    for (int s = 128; s > 0; s >>= 1) {
        if (tid < s) red[tid] += red[tid + s];
        __syncthreads();
    }
    if (tid == 0) g_ssum[row] = red[0];
}

// ======================= VLAD =======================
__global__ void __launch_bounds__(256)
vlad_kernel(const float* __restrict__ xenc, const float* __restrict__ cent) {
    __shared__ float s_sa[8][1024];
    __shared__ float s_in[1024];
    const int n = blockIdx.x >> 3;
    const int k0 = (blockIdx.x & 7) * 8;
    const int tid = threadIdx.x;

    for (int i = tid; i < 1024; i += 256) s_in[i] = g_invn[n * HWP + i];
    for (int i = tid; i < 8192; i += 256) {
        int kk = i >> 10, l = i & 1023;
        s_sa[kk][l] = g_sa[((size_t)n * 64 + k0 + kk) * HWP + l];
    }
    __syncthreads();

    const int warp = tid >> 5, lane = tid & 31;
    const float* xN = xenc + (size_t)n * CHN * HWP;

    for (int c = warp; c < 512; c += 8) {
        float acc[8];
#pragma unroll
        for (int kk = 0; kk < 8; kk++) acc[kk] = 0.f;
        for (int l = lane; l < 1024; l += 32) {
            float xv = xN[c * HWP + l] * s_in[l];
#pragma unroll
            for (int kk = 0; kk < 8; kk++) acc[kk] = fmaf(xv, s_sa[kk][l], acc[kk]);
        }
#pragma unroll
        for (int kk = 0; kk < 8; kk++) {
            float v = acc[kk];
#pragma unroll
            for (int o = 16; o > 0; o >>= 1) v += __shfl_down_sync(0xffffffffu, v, o);
            if (lane == 0) {
                int k = k0 + kk;
                g_vlad[((size_t)n * 64 + k) * 512 + c] =
                    v - g_ssum[n * 64 + k] * cent[k * 512 + c];
            }
        }
    }
}

// ======================= intra norm =======================
__global__ void intra_kernel(float* __restrict__ out_vlad) {
    int row = blockIdx.x;
    int tid = threadIdx.x;
    const float2* p = reinterpret_cast<const float2*>(g_vlad + (size_t)row * 512);
    float2 v = p[tid];
    float ssq = v.x * v.x + v.y * v.y;
    __shared__ float red[256];
    red[tid] = ssq;
    __syncthreads();
    for (int s = 128; s > 0; s >>= 1) {
        if (tid < s) red[tid] += red[tid + s];
        __syncthreads();
    }
    float ss = red[0];
    float inv = 1.f / fmaxf(sqrtf(ss), 1e-12f);
    float2* o = reinterpret_cast<float2*>(out_vlad + (size_t)row * 512);
    float2 w;
    w.x = v.x * inv;
    w.y = v.y * inv;
    o[tid] = w;
    if (tid == 0) g_rowss[row] = ss * inv * inv;
}

// ======================= global scale =======================
__global__ void gscale_kernel(float* __restrict__ out_vlad) {
    int n = blockIdx.x;
    int tid = threadIdx.x;
    __shared__ float red[64];
    __shared__ float gsc;
    if (tid < 64) red[tid] = g_rowss[n * 64 + tid];
    __syncthreads();
    if (tid == 0) {
        float t = 0.f;
        for (int i = 0; i < 64; i++) t += red[i];
        gsc = 1.f / fmaxf(sqrtf(t), 1e-12f);
    }
    __syncthreads();
    float g = gsc;
    float* o = out_vlad + (size_t)n * (KCL * CHN);
    for (int i = tid; i < KCL * CHN; i += 256) o[i] *= g;
}

// ======================= launcher =======================
extern "C" void kernel_launch(void* const* d_in, const int* in_sizes, int n_in,
                              void* d_out, int out_size) {
    const float* x     = (const float*)d_in[0];
    const float* w1    = (const float*)d_in[1];
    const float* gamma = (const float*)d_in[2];
    const float* beta  = (const float*)d_in[3];
    const float* mean  = (const float*)d_in[4];
    const float* var   = (const float*)d_in[5];
    const float* w2    = (const float*)d_in[6];
    const float* wa    = (const float*)d_in[7];
    const float* cent  = (const float*)d_in[8];

    float* out = (float*)d_out;
    float* out_vlad = out;
    float* out_xenc = out + (size_t)N_IMG * KCL * CHN;

    static int smem_set = 0;
    if (!smem_set) {
        cudaFuncSetAttribute(conv_mma_kernel,
                             cudaFuncAttributeMaxDynamicSharedMemorySize,
                             CONV_DSMEM);
        smem_set = 1;
    }

    prep_kernel<<<18432, 256>>>(w1, w2, gamma, beta, mean, var);
    pack_x_kernel<<<(N_IMG * CHN * HWP / 4) / 256, 256>>>(x);

    dim3 cgrid(8, 4, N_IMG);
    conv_mma_kernel<<<cgrid, 256, CONV_DSMEM>>>(nullptr, 1);
    conv_mma_kernel<<<cgrid, 256, CONV_DSMEM>>>(out_xenc, 2);

    assign_softmax_kernel<<<N_IMG * 8, 256>>>(out_xenc, wa);
    ssum_kernel<<<N_IMG * KCL, 256>>>();
    vlad_kernel<<<N_IMG * 8, 256>>>(out_xenc, cent);
    intra_kernel<<<N_IMG * KCL, 256>>>(out_vlad);
    gscale_kernel<<<N_IMG, 256>>>(out_vlad);
}